// round 12
// baseline (speedup 1.0000x reference)
#include <cuda_runtime.h>
#include <cuda_bf16.h>
#include <cstdint>

// Problem shape (fixed by dataset: X is [8192, 64] fp32)
#define NROWS 8192
#define DDIM  64

// -------- device scratch (static allocation only) ---------------------------
__device__ __nv_bfloat16 g_xbf[NROWS * DDIM];   // 1 MB, bf16 copy of X
__device__ float g_sq[NROWS];          // per-row ||x||^2 (fp32, exact)
__device__ float g_cp[256 * DDIM];     // partial column sums (256 blocks x 64)
__device__ float g_invl;               // log2(e) / (2*sigma^2)
__device__ unsigned int g_ctr;         // last-block counter (self-resetting)

__device__ __forceinline__ uint32_t smem_u32(const void* p) {
    uint32_t a;
    asm("{ .reg .u64 t; cvta.to.shared.u64 t, %1; cvt.u32.u64 %0, t; }"
        : "=r"(a) : "l"(p));
    return a;
}

__device__ __forceinline__ uint32_t pack_bf16x2(float lo, float hi) {
    __nv_bfloat162 h = __floats2bfloat162_rn(lo, hi);   // x=lo (low half), y=hi
    return *reinterpret_cast<uint32_t*>(&h);
}

// ---------- kernel 1 (fused): bf16 convert + ||x||^2 + column sums + finish --
// 256 blocks x 256 threads; block handles 32 rows. Last block to finish
// computes sigma^2 (deterministic fixed-order reduction) and resets the ctr.
__global__ void gk_pre(const float* __restrict__ X, int n) {
    __shared__ float scs[256];
    __shared__ bool s_last;
    int t = threadIdx.x;

    // Phase A: read 8 floats/thread; emit bf16 copy + row squared norms.
    {
        int row = blockIdx.x * 32 + (t >> 3);
        int sub = t & 7;
        const float4* p = reinterpret_cast<const float4*>(X + (size_t)row * DDIM + sub * 8);
        float4 a = p[0], b = p[1];
        uint4 w;
        w.x = pack_bf16x2(a.x, a.y); w.y = pack_bf16x2(a.z, a.w);
        w.z = pack_bf16x2(b.x, b.y); w.w = pack_bf16x2(b.z, b.w);
        *reinterpret_cast<uint4*>(g_xbf + (size_t)row * DDIM + sub * 8) = w;
        float s = a.x * a.x + a.y * a.y + a.z * a.z + a.w * a.w
                + b.x * b.x + b.y * b.y + b.z * b.z + b.w * b.w;
        s += __shfl_xor_sync(0xffffffffu, s, 1);
        s += __shfl_xor_sync(0xffffffffu, s, 2);
        s += __shfl_xor_sync(0xffffffffu, s, 4);
        if (sub == 0) g_sq[row] = s;
    }

    // Phase B: partial column sums for the mean vector.
    {
        int col = t & 63, stripe = t >> 6;     // 4 stripes x 8 rows
        int base = blockIdx.x * 32 + stripe * 8;
        float s = 0.f;
        #pragma unroll
        for (int r = 0; r < 8; r++)
            s += X[(size_t)(base + r) * DDIM + col];
        scs[t] = s;
        __syncthreads();
        if (t < 64) {
            float c = 0.f;
            #pragma unroll
            for (int st = 0; st < 4; st++) c += scs[st * 64 + t];
            g_cp[blockIdx.x * 64 + t] = c;
        }
    }

    // Phase C: last block computes stats (threadFenceReduction pattern).
    __threadfence();
    if (t == 0) {
        unsigned int v = atomicAdd(&g_ctr, 1u);
        s_last = (v == gridDim.x - 1);
    }
    __syncthreads();
    if (!s_last) return;
    __threadfence();

    // Deterministic finish with 256 threads.
    float q = 0.f;
    for (int r = t; r < n; r += 256) q += g_sq[r];   // fixed order per thread
    scs[t] = q;
    __syncthreads();
    for (int sft = 128; sft > 0; sft >>= 1) {
        if (t < sft) scs[t] += scs[t + sft];
        __syncthreads();
    }
    float meansq = scs[0] / (float)n;
    __syncthreads();
    if (t < 64) {
        float c = 0.f;
        #pragma unroll
        for (int b = 0; b < 256; b++) c += g_cp[b * 64 + t];
        scs[t] = c / (float)n;                 // mu_k
    }
    __syncthreads();
    if (t == 0) {
        float mu2 = 0.f;
        #pragma unroll
        for (int k = 0; k < 64; k++) mu2 += scs[k] * scs[k];
        float meand2 = 2.f * meansq - 2.f * mu2;   // ALPHA = 1
        g_invl = 1.44269504f / (2.f * meand2);     // log2(e)/(2 sigma^2)
        g_ctr = 0;                                 // reset for next graph replay
    }
}

// ------------------------- kernel 2: main tile kernel ------------------------
// Triangular grid (bi <= bj); 128x128 tile; bf16 mma.sync.m16n8k16 single pass.
// Operand tiles loaded from pre-converted g_xbf via cp.async.cg (16B units)
// into the proven conflict-free bf16 [128][72] layout (RF-free, L1-bypassed).
// Epilogue: R8 shape — direct primary STG.64 + mirror via SMEM transpose.
#define BM 128
#define BN 128
#define SBH 72          // bf16 per row in operand tiles (144 bytes)
#define TSTRIDE 132     // fp32 transpose staging stride

#define NTILE 64        // 8192 / 128
#define NTRI  (NTILE * (NTILE + 1) / 2)   // 2080

static constexpr int OFF_BS  = BM * SBH * 2;          // 18432
static constexpr int OFF_SQI = 2 * BM * SBH * 2;      // 36864
static constexpr int OFF_SQJ = OFF_SQI + 512;
static constexpr int SMEM_BYTES = BM * TSTRIDE * 4;   // 67584

#define CP_ASYNC16(dst, src) \
    asm volatile("cp.async.cg.shared.global [%0], [%1], 16;" \
        :: "r"(dst), "l"(src) : "memory")
#define CP_COMMIT() asm volatile("cp.async.commit_group;" ::: "memory")
#define CP_WAIT0()  asm volatile("cp.async.wait_group 0;" ::: "memory")

__device__ __forceinline__ void mma_bf16(float* c, const uint32_t* a, const uint32_t* b) {
    asm volatile(
        "mma.sync.aligned.m16n8k16.row.col.f32.bf16.bf16.f32 "
        "{%0,%1,%2,%3}, {%4,%5,%6,%7}, {%8,%9}, {%0,%1,%2,%3};"
        : "+f"(c[0]), "+f"(c[1]), "+f"(c[2]), "+f"(c[3])
        : "r"(a[0]), "r"(a[1]), "r"(a[2]), "r"(a[3]), "r"(b[0]), "r"(b[1]));
}

__device__ __forceinline__ float gauss_elem(float acc, float sj, float nsqi, float invl) {
    float u = fmaf(2.f, acc, nsqi - sj);   // u = 2*dot - sq_i - sq_j = -d2
    float a = fminf(u * invl, 0.f);        // = -max(d2,0)*log2e/(2 sigma^2)
    float r;
    asm("ex2.approx.f32 %0, %1;" : "=f"(r) : "f"(a));
    return r;
}

// Start index of triangle row bi: Start(bi) = bi*(2*NTILE+1-bi)/2
__device__ __forceinline__ int tri_start(int bi) {
    return (bi * (2 * NTILE + 1 - bi)) >> 1;
}

__global__ void __launch_bounds__(256, 2)
gk_main(float* __restrict__ out, int n) {
    extern __shared__ unsigned char smem[];
    unsigned char* Asb = smem;                 // bf16 [128][72]
    unsigned char* Bsb = smem + OFF_BS;        // bf16 [128][72]
    float* sqi = reinterpret_cast<float*>(smem + OFF_SQI);   // [128]
    float* sqj = reinterpret_cast<float*>(smem + OFF_SQJ);   // [128]
    float* T   = reinterpret_cast<float*>(smem);             // staging (reused)

    int tid = threadIdx.x;

    // ---- decode triangular block index: bi <= bj ---------------------------
    int t = blockIdx.x;
    int bi = (int)((129.0f - sqrtf(16641.0f - 8.0f * (float)t)) * 0.5f);
    if (bi < 0) bi = 0;
    if (bi > NTILE - 1) bi = NTILE - 1;
    while (bi + 1 <= NTILE - 1 && tri_start(bi + 1) <= t) bi++;
    while (tri_start(bi) > t) bi--;
    int bj = bi + (t - tri_start(bi));

    float invl = g_invl;   // hoisted: latency hides under tile load + GEMM

    // ---- operand tiles via cp.async.cg from pre-converted bf16 -------------
    {
        uint32_t sa = smem_u32(Asb);
        uint32_t sb = smem_u32(Bsb);
        const __nv_bfloat16* gA = g_xbf + (size_t)bi * BM * DDIM;
        const __nv_bfloat16* gB = g_xbf + (size_t)bj * BN * DDIM;
        #pragma unroll
        for (int it = 0; it < 4; it++) {
            int e = tid + 256 * it;            // 1024 16B-units per tile
            int row = e >> 3, u = e & 7;
            int doff = row * (SBH * 2) + u * 16;
            const __nv_bfloat16* srcA = gA + row * DDIM + u * 8;
            const __nv_bfloat16* srcB = gB + row * DDIM + u * 8;
            CP_ASYNC16(sa + doff, srcA);
            CP_ASYNC16(sb + doff, srcB);
        }
        CP_COMMIT();
        if (tid < 128) sqi[tid] = g_sq[bi * BM + tid];
        else           sqj[tid - 128] = g_sq[bj * BN + (tid - 128)];
        CP_WAIT0();
    }
    __syncthreads();

    // ---- warp-level bf16 GEMM (m16n8k16), warp tile 32x64, 4(m)x2(n) ------
    int wid = tid >> 5, lane = tid & 31;
    int wm = wid & 3, wn = wid >> 2;
    int gq = lane >> 2, q4 = lane & 3;

    float acc[2][8][4];
    #pragma unroll
    for (int mt = 0; mt < 2; mt++)
        #pragma unroll
        for (int nt = 0; nt < 8; nt++)
            #pragma unroll
            for (int r = 0; r < 4; r++) acc[mt][nt][r] = 0.f;

    #pragma unroll
    for (int kc = 0; kc < 4; kc++) {
        int kb = kc * 32 + q4 * 4;             // byte offset within k-chunk
        uint32_t afr[2][4];
        #pragma unroll
        for (int mt = 0; mt < 2; mt++) {
            int row = wm * 32 + mt * 16 + gq;
            const unsigned char* base0 = Asb + row * (SBH * 2) + kb;
            const unsigned char* base1 = Asb + (row + 8) * (SBH * 2) + kb;
            afr[mt][0] = *reinterpret_cast<const uint32_t*>(base0);
            afr[mt][1] = *reinterpret_cast<const uint32_t*>(base1);
            afr[mt][2] = *reinterpret_cast<const uint32_t*>(base0 + 16);
            afr[mt][3] = *reinterpret_cast<const uint32_t*>(base1 + 16);
        }
        uint32_t bfr[8][2];
        #pragma unroll
        for (int nt = 0; nt < 8; nt++) {
            int col = wn * 64 + nt * 8 + gq;
            const unsigned char* base = Bsb + col * (SBH * 2) + kb;
            bfr[nt][0] = *reinterpret_cast<const uint32_t*>(base);
            bfr[nt][1] = *reinterpret_cast<const uint32_t*>(base + 16);
        }
        #pragma unroll
        for (int mt = 0; mt < 2; mt++)
            #pragma unroll
            for (int nt = 0; nt < 8; nt++)
                mma_bf16(acc[mt][nt], afr[mt], bfr[nt]);
    }

    // ---- epilogue: transform acc in place, direct STG of primary tile ------
    #pragma unroll
    for (int mt = 0; mt < 2; mt++) {
        #pragma unroll
        for (int rr = 0; rr < 2; rr++) {
            int rloc = wm * 32 + mt * 16 + gq + rr * 8;
            int grow = bi * BM + rloc;
            float nsqi = -sqi[rloc];
            float* orow = out + (size_t)grow * n + bj * BN;
            #pragma unroll
            for (int nt = 0; nt < 8; nt++) {
                int c0 = wn * 64 + nt * 8 + 2 * q4;
                float2 v;
                v.x = gauss_elem(acc[mt][nt][rr * 2 + 0], sqj[c0],     nsqi, invl);
                v.y = gauss_elem(acc[mt][nt][rr * 2 + 1], sqj[c0 + 1], nsqi, invl);
                acc[mt][nt][rr * 2 + 0] = v.x;     // keep for mirror
                acc[mt][nt][rr * 2 + 1] = v.y;
                *reinterpret_cast<float2*>(orow + c0) = v;
            }
        }
    }

    // ---- mirror tile: transpose through SMEM, coalesced STG ---------------
    if (bi != bj) {
        __syncthreads();   // operand tiles dead -> reuse as staging T
        #pragma unroll
        for (int mt = 0; mt < 2; mt++) {
            #pragma unroll
            for (int rr = 0; rr < 2; rr++) {
                int rloc = wm * 32 + mt * 16 + gq + rr * 8;
                #pragma unroll
                for (int nt = 0; nt < 8; nt++) {
                    int c0 = wn * 64 + nt * 8 + 2 * q4;
                    T[(c0    ) * TSTRIDE + rloc] = acc[mt][nt][rr * 2 + 0];
                    T[(c0 + 1) * TSTRIDE + rloc] = acc[mt][nt][rr * 2 + 1];
                }
            }
        }
        __syncthreads();
        #pragma unroll
        for (int iter = 0; iter < 16; iter++) {
            int r = iter * 8 + wid;
            float4 v = *reinterpret_cast<const float4*>(&T[r * TSTRIDE + 4 * lane]);
            float* orow = out + (size_t)(bj * BN + r) * n + bi * BM + 4 * lane;
            *reinterpret_cast<float4*>(orow) = v;
        }
    }
}

// ------------------------------ launch ---------------------------------------
extern "C" void kernel_launch(void* const* d_in, const int* in_sizes, int n_in,
                              void* d_out, int out_size) {
    const float* X = (const float*)d_in[0];
    int n = in_sizes[0] / DDIM;          // 8192
    float* out = (float*)d_out;

    cudaFuncSetAttribute(gk_main, cudaFuncAttributeMaxDynamicSharedMemorySize,
                         SMEM_BYTES);

    gk_pre<<<256, 256>>>(X, n);
    gk_main<<<NTRI, 256, SMEM_BYTES>>>(out, n);
}

// round 14
// speedup vs baseline: 1.4666x; 1.4666x over previous
#include <cuda_runtime.h>
#include <cuda_bf16.h>
#include <cstdint>

// Problem shape (fixed by dataset: X is [8192, 64] fp32)
#define NROWS 8192
#define DDIM  64

// -------- device scratch (static allocation only) ---------------------------
__device__ float g_sq[NROWS];         // per-row ||x||^2 (fp32, exact)
__device__ float g_cp[256 * DDIM];    // partial column sums (256 blocks x 64)
__device__ float g_invl;              // log2(e) / (2*sigma^2)

// ---------- kernel 1 (fused): per-row ||x||^2 + partial column sums ---------
// 256 blocks x 256 threads; block handles 32 rows (8 KB chunk).
__global__ void gk_pre(const float* __restrict__ X) {
    __shared__ float scs[256];
    int t = threadIdx.x;

    // Phase A: row squared norms. 8 threads per row, 8 floats each.
    {
        int row = blockIdx.x * 32 + (t >> 3);
        int sub = t & 7;
        const float4* p = reinterpret_cast<const float4*>(X + (size_t)row * DDIM + sub * 8);
        float4 a = p[0], b = p[1];
        float s = a.x * a.x + a.y * a.y + a.z * a.z + a.w * a.w
                + b.x * b.x + b.y * b.y + b.z * b.z + b.w * b.w;
        s += __shfl_xor_sync(0xffffffffu, s, 1);
        s += __shfl_xor_sync(0xffffffffu, s, 2);
        s += __shfl_xor_sync(0xffffffffu, s, 4);
        if (sub == 0) g_sq[row] = s;
    }

    // Phase B: partial column sums for the mean vector.
    {
        int col = t & 63, stripe = t >> 6;     // 4 stripes x 8 rows
        int base = blockIdx.x * 32 + stripe * 8;
        float s = 0.f;
        #pragma unroll
        for (int r = 0; r < 8; r++)
            s += X[(size_t)(base + r) * DDIM + col];
        scs[t] = s;
        __syncthreads();
        if (t < 64) {
            float c = 0.f;
            #pragma unroll
            for (int st = 0; st < 4; st++) c += scs[st * 64 + t];
            g_cp[blockIdx.x * 64 + t] = c;
        }
    }
}

// --------------- kernel 2: finish stats -> log2e/(2 sigma^2) ----------------
// mean(d2) = 2*mean(sq) - 2*||mu||^2 (clamp correction is O(1e-9) relative)
__global__ void gk_finish(int n) {
    __shared__ float ssq[1024];
    __shared__ float smu[64];
    int t = threadIdx.x;
    float q = 0.f;
    for (int r = t; r < n; r += 1024) q += g_sq[r];
    ssq[t] = q;
    __syncthreads();
    for (int sft = 512; sft > 0; sft >>= 1) {
        if (t < sft) ssq[t] += ssq[t + sft];
        __syncthreads();
    }
    if (t < 64) {
        float c = 0.f;
        #pragma unroll
        for (int b = 0; b < 256; b++) c += g_cp[b * 64 + t];
        smu[t] = c / (float)n;                 // mu_k
    }
    __syncthreads();
    if (t == 0) {
        float mu2 = 0.f;
        #pragma unroll
        for (int k = 0; k < 64; k++) mu2 += smu[k] * smu[k];
        float meansq = ssq[0] / (float)n;
        float meand2 = 2.f * meansq - 2.f * mu2;   // ALPHA = 1
        g_invl = 1.44269504f / (2.f * meand2);     // log2(e)/(2 sigma^2)
    }
}

// ------------------------- kernel 3: main tile kernel ------------------------
// Triangular grid (bi <= bj); 128x128 tile; bf16 mma.sync.m16n8k16 single pass.
// Operand tiles: fp32 LDG.128 -> cvt -> bf16 [128][72] STS.128 (R8 proven).
// Primary tile: direct STG.64. Mirror tile: direct register STG.32 scatter
// (4 rows x 32B contiguous per warp-inst; L2 merges lines) — no staging,
// no extra barriers.
#define BM 128
#define BN 128
#define SBH 72          // bf16 per row in operand tiles (144 bytes)

#define NTILE 64        // 8192 / 128
#define NTRI  (NTILE * (NTILE + 1) / 2)   // 2080

static constexpr int OFF_BS  = BM * SBH * 2;          // 18432
static constexpr int OFF_SQI = 2 * BM * SBH * 2;      // 36864
static constexpr int OFF_SQJ = OFF_SQI + 512;
static constexpr int SMEM_BYTES = OFF_SQJ + 512;      // 37888

__device__ __forceinline__ void mma_bf16(float* c, const uint32_t* a, const uint32_t* b) {
    asm volatile(
        "mma.sync.aligned.m16n8k16.row.col.f32.bf16.bf16.f32 "
        "{%0,%1,%2,%3}, {%4,%5,%6,%7}, {%8,%9}, {%0,%1,%2,%3};"
        : "+f"(c[0]), "+f"(c[1]), "+f"(c[2]), "+f"(c[3])
        : "r"(a[0]), "r"(a[1]), "r"(a[2]), "r"(a[3]), "r"(b[0]), "r"(b[1]));
}

__device__ __forceinline__ float gauss_elem(float acc, float sj, float nsqi, float invl) {
    float u = fmaf(2.f, acc, nsqi - sj);   // u = 2*dot - sq_i - sq_j = -d2
    float a = fminf(u * invl, 0.f);        // = -max(d2,0)*log2e/(2 sigma^2)
    float r;
    asm("ex2.approx.f32 %0, %1;" : "=f"(r) : "f"(a));
    return r;
}

// Start index of triangle row bi: Start(bi) = bi*(2*NTILE+1-bi)/2
__device__ __forceinline__ int tri_start(int bi) {
    return (bi * (2 * NTILE + 1 - bi)) >> 1;
}

__device__ __forceinline__ uint32_t pack_bf16x2(float lo, float hi) {
    __nv_bfloat162 h = __floats2bfloat162_rn(lo, hi);   // x=lo (low half), y=hi
    return *reinterpret_cast<uint32_t*>(&h);
}

__global__ void __launch_bounds__(256, 2)
gk_main(const float* __restrict__ X, float* __restrict__ out, int n) {
    extern __shared__ unsigned char smem[];
    unsigned char* Asb = smem;                 // bf16 [128][72]
    unsigned char* Bsb = smem + OFF_BS;        // bf16 [128][72]
    float* sqi = reinterpret_cast<float*>(smem + OFF_SQI);   // [128]
    float* sqj = reinterpret_cast<float*>(smem + OFF_SQJ);   // [128]

    int tid = threadIdx.x;

    // ---- decode triangular block index: bi <= bj ---------------------------
    int t = blockIdx.x;
    int bi = (int)((129.0f - sqrtf(16641.0f - 8.0f * (float)t)) * 0.5f);
    if (bi < 0) bi = 0;
    if (bi > NTILE - 1) bi = NTILE - 1;
    while (bi + 1 <= NTILE - 1 && tri_start(bi + 1) <= t) bi++;
    while (tri_start(bi) > t) bi--;
    int bj = bi + (t - tri_start(bi));

    float invl = g_invl;   // hoisted: latency hides under tile load + GEMM

    // ---- cooperative load: fp32 -> bf16 tiles (conflict-free STS.128) ------
    {
        const float* gA = X + (size_t)bi * BM * DDIM;
        const float* gB = X + (size_t)bj * BN * DDIM;
        #pragma unroll
        for (int it = 0; it < 4; it++) {
            int e = tid + 256 * it;
            int row = e >> 3, u = e & 7;
            const float4* pa = reinterpret_cast<const float4*>(gA + row * DDIM + u * 8);
            const float4* pb = reinterpret_cast<const float4*>(gB + row * DDIM + u * 8);
            float4 a0 = pa[0], a1 = pa[1];
            float4 b0 = pb[0], b1 = pb[1];
            uint4 wa, wb;
            wa.x = pack_bf16x2(a0.x, a0.y); wa.y = pack_bf16x2(a0.z, a0.w);
            wa.z = pack_bf16x2(a1.x, a1.y); wa.w = pack_bf16x2(a1.z, a1.w);
            wb.x = pack_bf16x2(b0.x, b0.y); wb.y = pack_bf16x2(b0.z, b0.w);
            wb.z = pack_bf16x2(b1.x, b1.y); wb.w = pack_bf16x2(b1.z, b1.w);
            int off = row * (SBH * 2) + u * 16;
            *reinterpret_cast<uint4*>(Asb + off) = wa;
            *reinterpret_cast<uint4*>(Bsb + off) = wb;
        }
        if (tid < 128) sqi[tid] = g_sq[bi * BM + tid];
        else           sqj[tid - 128] = g_sq[bj * BN + (tid - 128)];
    }
    __syncthreads();

    // ---- warp-level bf16 GEMM (m16n8k16), warp tile 32x64, 4(m)x2(n) ------
    int wid = tid >> 5, lane = tid & 31;
    int wm = wid & 3, wn = wid >> 2;
    int gq = lane >> 2, q4 = lane & 3;

    float acc[2][8][4];
    #pragma unroll
    for (int mt = 0; mt < 2; mt++)
        #pragma unroll
        for (int nt = 0; nt < 8; nt++)
            #pragma unroll
            for (int r = 0; r < 4; r++) acc[mt][nt][r] = 0.f;

    #pragma unroll
    for (int kc = 0; kc < 4; kc++) {
        int kb = kc * 32 + q4 * 4;             // byte offset within k-chunk
        uint32_t afr[2][4];
        #pragma unroll
        for (int mt = 0; mt < 2; mt++) {
            int row = wm * 32 + mt * 16 + gq;
            const unsigned char* base0 = Asb + row * (SBH * 2) + kb;
            const unsigned char* base1 = Asb + (row + 8) * (SBH * 2) + kb;
            afr[mt][0] = *reinterpret_cast<const uint32_t*>(base0);
            afr[mt][1] = *reinterpret_cast<const uint32_t*>(base1);
            afr[mt][2] = *reinterpret_cast<const uint32_t*>(base0 + 16);
            afr[mt][3] = *reinterpret_cast<const uint32_t*>(base1 + 16);
        }
        uint32_t bfr[8][2];
        #pragma unroll
        for (int nt = 0; nt < 8; nt++) {
            int col = wn * 64 + nt * 8 + gq;
            const unsigned char* base = Bsb + col * (SBH * 2) + kb;
            bfr[nt][0] = *reinterpret_cast<const uint32_t*>(base);
            bfr[nt][1] = *reinterpret_cast<const uint32_t*>(base + 16);
        }
        #pragma unroll
        for (int mt = 0; mt < 2; mt++)
            #pragma unroll
            for (int nt = 0; nt < 8; nt++)
                mma_bf16(acc[mt][nt], afr[mt], bfr[nt]);
    }

    // ---- epilogue: transform acc in place, direct STG of primary tile ------
    #pragma unroll
    for (int mt = 0; mt < 2; mt++) {
        #pragma unroll
        for (int rr = 0; rr < 2; rr++) {
            int rloc = wm * 32 + mt * 16 + gq + rr * 8;
            int grow = bi * BM + rloc;
            float nsqi = -sqi[rloc];
            float* orow = out + (size_t)grow * n + bj * BN;
            #pragma unroll
            for (int nt = 0; nt < 8; nt++) {
                int c0 = wn * 64 + nt * 8 + 2 * q4;
                float2 v;
                v.x = gauss_elem(acc[mt][nt][rr * 2 + 0], sqj[c0],     nsqi, invl);
                v.y = gauss_elem(acc[mt][nt][rr * 2 + 1], sqj[c0 + 1], nsqi, invl);
                acc[mt][nt][rr * 2 + 0] = v.x;     // keep for mirror
                acc[mt][nt][rr * 2 + 1] = v.y;
                *reinterpret_cast<float2*>(orow + c0) = v;
            }
        }
    }

    // ---- mirror tile: direct register scatter (no staging, no barriers) ----
    // Per warp-inst: 4 distinct output rows (q4), each 8 consecutive floats
    // (gq fastest) = 32B contiguous segments; warp's nt/mt loop completes
    // 128B lines in L2 before eviction.
    if (bi != bj) {
        float* obase = out + (size_t)bj * BN * n + bi * BM;
        #pragma unroll
        for (int mt = 0; mt < 2; mt++) {
            #pragma unroll
            for (int rr = 0; rr < 2; rr++) {
                int rloc = wm * 32 + mt * 16 + gq + rr * 8;
                #pragma unroll
                for (int nt = 0; nt < 8; nt++) {
                    int c0 = wn * 64 + nt * 8 + 2 * q4;
                    obase[(size_t)c0 * n + rloc]       = acc[mt][nt][rr * 2 + 0];
                    obase[(size_t)(c0 + 1) * n + rloc] = acc[mt][nt][rr * 2 + 1];
                }
            }
        }
    }
}

// ------------------------------ launch ---------------------------------------
extern "C" void kernel_launch(void* const* d_in, const int* in_sizes, int n_in,
                              void* d_out, int out_size) {
    const float* X = (const float*)d_in[0];
    int n = in_sizes[0] / DDIM;          // 8192
    float* out = (float*)d_out;

    cudaFuncSetAttribute(gk_main, cudaFuncAttributeMaxDynamicSharedMemorySize,
                         SMEM_BYTES);

    gk_pre<<<256, 256>>>(X);
    gk_finish<<<1, 1024>>>(n);
    gk_main<<<NTRI, 256, SMEM_BYTES>>>(X, out, n);
}